// round 1
// baseline (speedup 1.0000x reference)
#include <cuda_runtime.h>
#include <math.h>

#define B   16
#define H   1024
#define W   1024
#define HS  512
#define WS  512
#define HC  256
#define WC  256
#define KP  32
#define CROP 160
#define NCH 32
#define CANDMAX 65536

// ---- scratch (device globals; no runtime allocation allowed) ----
__device__ float g_rimg[B * HS * WS];            // 16 MB
__device__ float g_h[B * NCH * HC * WC];         // 134 MB, [b][c][y][x]
__device__ float g_cms[B * HC * WC];             // 4 MB
__device__ unsigned long long g_cand[B * CANDMAX];
__device__ int   g_cnt[B];
__device__ float g_centers[B * KP * 3];          // cx, cy, validf

// ============================================================
// Stage 1: antialiased bilinear 2x downsample (jax semantics)
// ============================================================
__device__ __forceinline__ void resize_taps(int o, int n, int* idx, float* w) {
    const float wb = 0.375f / 0.875f;   // edge-renormalized
    const float ws = 0.125f / 0.875f;
    if (o == 0) {
        idx[0] = 0; w[0] = 0.0f;
        idx[1] = 0; w[1] = wb;
        idx[2] = 1; w[2] = wb;
        idx[3] = 2; w[3] = ws;
    } else if (o == n - 1) {
        idx[0] = 2 * o - 1; w[0] = ws;
        idx[1] = 2 * o;     w[1] = wb;
        idx[2] = 2 * o + 1; w[2] = wb;
        idx[3] = 2 * o + 1; w[3] = 0.0f;
    } else {
        idx[0] = 2 * o - 1; w[0] = 0.125f;
        idx[1] = 2 * o;     w[1] = 0.375f;
        idx[2] = 2 * o + 1; w[2] = 0.375f;
        idx[3] = 2 * o + 2; w[3] = 0.125f;
    }
}

__global__ void resize_kernel(const float* __restrict__ img) {
    int gid = blockIdx.x * blockDim.x + threadIdx.x;
    if (gid < B) g_cnt[gid] = 0;     // reset candidate counters each replay
    if (gid >= B * HS * WS) return;
    int b   = gid / (HS * WS);
    int rem = gid % (HS * WS);
    int oy  = rem / WS;
    int ox  = rem % WS;

    int iy[4], ix[4];
    float wy[4], wx[4];
    resize_taps(oy, HS, iy, wy);
    resize_taps(ox, WS, ix, wx);

    const float* ib = img + (long long)b * H * W;
    float acc = 0.0f;
#pragma unroll
    for (int tx = 0; tx < 4; tx++) {
        float s = 0.0f;
#pragma unroll
        for (int ty = 0; ty < 4; ty++)
            s += wy[ty] * __ldg(ib + iy[ty] * W + ix[tx]);
        acc += wx[tx] * s;
    }
    g_rimg[gid] = acc;
}

// ============================================================
// Stage 2: conv1 5x5 stride 2 SAME (pad lo=1, hi=2), 1->32, ReLU
// output layout [b][c][y][x]
// ============================================================
__global__ void conv1_kernel(const float* __restrict__ w1, const float* __restrict__ b1) {
    __shared__ float tile[35 * 35];
    __shared__ float ws[800];
    __shared__ float bs[32];

    int b   = blockIdx.z;
    int py0 = blockIdx.y * 16;
    int px0 = blockIdx.x * 16;
    int tid = threadIdx.x;   // 256

    for (int i = tid; i < 800; i += 256) ws[i] = w1[i];
    if (tid < 32) bs[tid] = b1[tid];
    for (int i = tid; i < 35 * 35; i += 256) {
        int r = i / 35, c = i % 35;
        int gy = 2 * py0 - 1 + r;
        int gx = 2 * px0 - 1 + c;
        float v = 0.0f;
        if (gy >= 0 && gy < HS && gx >= 0 && gx < WS)
            v = g_rimg[(b * HS + gy) * WS + gx];
        tile[i] = v;
    }
    __syncthreads();

    int ty = tid / 16, tx = tid % 16;
    float acc[NCH];
#pragma unroll
    for (int c = 0; c < NCH; c++) acc[c] = 0.0f;

#pragma unroll
    for (int u = 0; u < 5; u++) {
#pragma unroll
        for (int v = 0; v < 5; v++) {
            float s = tile[(2 * ty + u) * 35 + (2 * tx + v)];
            const float* wp = &ws[(u * 5 + v) * NCH];
#pragma unroll
            for (int c = 0; c < NCH; c++) acc[c] += s * wp[c];
        }
    }
    int py = py0 + ty, px = px0 + tx;
#pragma unroll
    for (int c = 0; c < NCH; c++) {
        float hv = acc[c] + bs[c];
        hv = hv > 0.0f ? hv : 0.0f;
        g_h[((b * NCH + c) * HC + py) * WC + px] = hv;
    }
}

// ============================================================
// Stage 3: conv2 5x5 stride 1 SAME (pad 2), 32->1, sigmoid
// ============================================================
__global__ void conv2_kernel(const float* __restrict__ w2, const float* __restrict__ b2) {
    __shared__ float hs[16 * 400];   // 16 channels x 20x20 tile
    __shared__ float ws[800];

    int b   = blockIdx.z;
    int py0 = blockIdx.y * 16;
    int px0 = blockIdx.x * 16;
    int tid = threadIdx.x;
    int ty = tid / 16, tx = tid % 16;

    for (int i = tid; i < 800; i += 256) ws[i] = w2[i];

    float acc = 0.0f;
    for (int c0 = 0; c0 < NCH; c0 += 16) {
        __syncthreads();
        for (int i = tid; i < 16 * 400; i += 256) {
            int c   = i / 400;
            int r   = (i % 400) / 20;
            int col = i % 20;
            int gy = py0 - 2 + r;
            int gx = px0 - 2 + col;
            float v = 0.0f;
            if (gy >= 0 && gy < HC && gx >= 0 && gx < WC)
                v = g_h[((b * NCH + c0 + c) * HC + gy) * WC + gx];
            hs[i] = v;
        }
        __syncthreads();
        for (int c = 0; c < 16; c++) {
#pragma unroll
            for (int u = 0; u < 5; u++)
#pragma unroll
                for (int v = 0; v < 5; v++)
                    acc += hs[c * 400 + (ty + u) * 20 + (tx + v)] *
                           ws[(u * 5 + v) * NCH + c0 + c];
        }
    }
    float x = acc + b2[0];
    float s = 1.0f / (1.0f + expf(-x));
    g_cms[(b * HC + py0 + ty) * WC + px0 + tx] = s;
}

// ============================================================
// Stage 4: 3x3 NMS + threshold -> packed candidates
// key = (float_bits(val) << 32) | ~idx  (max-key == jax top_k order)
// ============================================================
__global__ void nms_kernel() {
    int gid = blockIdx.x * blockDim.x + threadIdx.x;
    if (gid >= B * HC * WC) return;
    int b   = gid / (HC * WC);
    int rem = gid % (HC * WC);
    int p = rem / WC, q = rem % WC;
    float v = g_cms[gid];
    if (!(v > 0.2f)) return;
    bool peak = true;
#pragma unroll
    for (int dy = -1; dy <= 1; dy++) {
#pragma unroll
        for (int dx = -1; dx <= 1; dx++) {
            if (dy == 0 && dx == 0) continue;
            int y = p + dy, x = q + dx;
            if (y >= 0 && y < HC && x >= 0 && x < WC) {
                if (g_cms[(b * HC + y) * WC + x] > v) peak = false;
            }
        }
    }
    if (peak) {
        int pos = atomicAdd(&g_cnt[b], 1);
        unsigned int fb = __float_as_uint(v);   // positive floats: bit-monotonic
        unsigned long long key =
            ((unsigned long long)fb << 32) | (unsigned int)(~(unsigned int)rem);
        g_cand[b * CANDMAX + pos] = key;
    }
}

// ============================================================
// Stage 5: top-32 per batch + integral refinement (5x5 patch)
// ============================================================
__global__ void topk_kernel(float* __restrict__ out_offs,
                            float* __restrict__ out_vals,
                            float* __restrict__ out_valid) {
    __shared__ unsigned long long red[256];
    __shared__ unsigned long long sel[KP];
    __shared__ unsigned long long prevs;

    int b = blockIdx.x;
    int tid = threadIdx.x;
    int n = g_cnt[b];
    if (n > CANDMAX) n = CANDMAX;
    if (tid == 0) prevs = 0xFFFFFFFFFFFFFFFFULL;
    __syncthreads();

    for (int k = 0; k < KP; k++) {
        unsigned long long prev = prevs;
        unsigned long long local = 0ULL;
        for (int i = tid; i < n; i += 256) {
            unsigned long long key = g_cand[b * CANDMAX + i];
            if (key < prev && key > local) local = key;
        }
        red[tid] = local;
        __syncthreads();
        for (int s = 128; s > 0; s >>= 1) {
            if (tid < s && red[tid + s] > red[tid]) red[tid] = red[tid + s];
            __syncthreads();
        }
        if (tid == 0) { sel[k] = red[0]; prevs = red[0]; }
        __syncthreads();
    }

    if (tid < KP) {
        int k = tid;
        unsigned long long key = sel[k];
        float cx = 80.0f, cy = 80.0f, val = 0.0f, vf = 0.0f;
        float offx = 0.0f, offy = 0.0f;
        if (key != 0ULL) {
            vf = 1.0f;
            unsigned int idx = ~(unsigned int)(key & 0xFFFFFFFFULL);
            val = __uint_as_float((unsigned int)(key >> 32));
            int py = idx / WC, px = idx % WC;
            float sum = 0.0f, sx = 0.0f, sy = 0.0f;
            for (int dy = -2; dy <= 2; dy++) {
                for (int dx = -2; dx <= 2; dx++) {
                    int yy = py + dy, xx = px + dx;
                    if (yy >= 0 && yy < HC && xx >= 0 && xx < WC) {
                        float pv = g_cms[(b * HC + yy) * WC + xx];
                        sum += pv;
                        sx += pv * (float)dx;
                        sy += pv * (float)dy;
                    }
                }
            }
            float g = sum + 1e-12f;
            float dxo = sx / g;
            float dyo = sy / g;
            cx = ((float)px + dxo) * 2.0f / 0.5f;
            cy = ((float)py + dyo) * 2.0f / 0.5f;
            offx = cx - 80.0f;
            offy = cy - 80.0f;
        }
        out_vals[b * KP + k] = val;
        out_valid[b * KP + k] = vf;
        out_offs[(b * KP + k) * 2 + 0] = offx;
        out_offs[(b * KP + k) * 2 + 1] = offy;
        g_centers[(b * KP + k) * 3 + 0] = cx;
        g_centers[(b * KP + k) * 3 + 1] = cy;
        g_centers[(b * KP + k) * 3 + 2] = vf;
    }
}

// ============================================================
// Stage 6: bilinear 160x160 crops from full image
// ============================================================
__global__ void crop_kernel(const float* __restrict__ img, float* __restrict__ out) {
    int b = blockIdx.z, k = blockIdx.y, i = blockIdx.x;
    int j = threadIdx.x;

    float cx = g_centers[(b * KP + k) * 3 + 0];
    float cy = g_centers[(b * KP + k) * 3 + 1];
    float vf = g_centers[(b * KP + k) * 3 + 2];

    float sy = (cy - 79.5f) + (float)i;
    float sx = (cx - 79.5f) + (float)j;
    float y0 = floorf(sy), x0 = floorf(sx);
    float wy = sy - y0, wx = sx - x0;
    int y0i = (int)y0, x0i = (int)x0;
    int yi0 = min(max(y0i, 0), H - 1);
    int yi1 = min(max(y0i + 1, 0), H - 1);
    int xi0 = min(max(x0i, 0), W - 1);
    int xi1 = min(max(x0i + 1, 0), W - 1);

    const float* ib = img + (long long)b * H * W;
    float v00 = __ldg(ib + yi0 * W + xi0);
    float v01 = __ldg(ib + yi0 * W + xi1);
    float v10 = __ldg(ib + yi1 * W + xi0);
    float v11 = __ldg(ib + yi1 * W + xi1);

    float top = v00 * (1.0f - wx) + v01 * wx;
    float bot = v10 * (1.0f - wx) + v11 * wx;
    float val = top * (1.0f - wy) + bot * wy;

    float inr = (sy >= 0.0f && sy <= (float)(H - 1) &&
                 sx >= 0.0f && sx <= (float)(W - 1)) ? 1.0f : 0.0f;

    out[(((long long)(b * KP + k)) * CROP + i) * CROP + j] = val * inr * vf;
}

// ============================================================
extern "C" void kernel_launch(void* const* d_in, const int* in_sizes, int n_in,
                              void* d_out, int out_size) {
    const float* img = (const float*)d_in[0];
    const float* w1  = (const float*)d_in[1];
    const float* b1  = (const float*)d_in[2];
    const float* w2  = (const float*)d_in[3];
    const float* b2  = (const float*)d_in[4];

    float* out = (float*)d_out;
    float* out_crops = out;
    float* out_offs  = out + (long long)B * KP * CROP * CROP;
    float* out_vals  = out_offs + B * KP * 2;
    float* out_valid = out_vals + B * KP;

    int n1 = B * HS * WS;
    resize_kernel<<<(n1 + 255) / 256, 256>>>(img);

    dim3 gconv(WC / 16, HC / 16, B);
    conv1_kernel<<<gconv, 256>>>(w1, b1);
    conv2_kernel<<<gconv, 256>>>(w2, b2);

    int n2 = B * HC * WC;
    nms_kernel<<<(n2 + 255) / 256, 256>>>();

    topk_kernel<<<B, 256>>>(out_offs, out_vals, out_valid);

    dim3 gcrop(CROP, KP, B);
    crop_kernel<<<gcrop, CROP>>>(img, out_crops);
}

// round 3
// speedup vs baseline: 1.1065x; 1.1065x over previous
#include <cuda_runtime.h>
#include <math.h>

#define B   16
#define H   1024
#define W   1024
#define HS  512
#define WS  512
#define HC  256
#define WC  256
#define KP  32
#define CROP 160
#define NCH 32
#define CANDMAX 65536

// ---- scratch (device globals; no runtime allocation allowed) ----
__device__ float g_rimg[B * HS * WS];            // 16 MB
__device__ float g_h[B * NCH * HC * WC];         // 134 MB, [b][c][y][x]
__device__ float g_cms[B * HC * WC];             // 4 MB
__device__ unsigned long long g_cand[B * CANDMAX];
__device__ int   g_cnt[B];
__device__ float g_centers[B * KP * 3];          // cx, cy, validf

// ============================================================
// Stage 1: antialiased bilinear 2x downsample (jax semantics)
// ============================================================
__device__ __forceinline__ void resize_taps(int o, int n, int* idx, float* w) {
    const float wb = 0.375f / 0.875f;   // edge-renormalized
    const float ws = 0.125f / 0.875f;
    if (o == 0) {
        idx[0] = 0; w[0] = 0.0f;
        idx[1] = 0; w[1] = wb;
        idx[2] = 1; w[2] = wb;
        idx[3] = 2; w[3] = ws;
    } else if (o == n - 1) {
        idx[0] = 2 * o - 1; w[0] = ws;
        idx[1] = 2 * o;     w[1] = wb;
        idx[2] = 2 * o + 1; w[2] = wb;
        idx[3] = 2 * o + 1; w[3] = 0.0f;
    } else {
        idx[0] = 2 * o - 1; w[0] = 0.125f;
        idx[1] = 2 * o;     w[1] = 0.375f;
        idx[2] = 2 * o + 1; w[2] = 0.375f;
        idx[3] = 2 * o + 2; w[3] = 0.125f;
    }
}

__global__ void resize_kernel(const float* __restrict__ img) {
    int gid = blockIdx.x * blockDim.x + threadIdx.x;
    if (gid < B) g_cnt[gid] = 0;     // reset candidate counters each replay
    if (gid >= B * HS * WS) return;
    int b   = gid / (HS * WS);
    int rem = gid % (HS * WS);
    int oy  = rem / WS;
    int ox  = rem % WS;

    int iy[4], ix[4];
    float wy[4], wx[4];
    resize_taps(oy, HS, iy, wy);
    resize_taps(ox, WS, ix, wx);

    const float* ib = img + (long long)b * H * W;
    float acc = 0.0f;
#pragma unroll
    for (int tx = 0; tx < 4; tx++) {
        float s = 0.0f;
#pragma unroll
        for (int ty = 0; ty < 4; ty++)
            s += wy[ty] * __ldg(ib + iy[ty] * W + ix[tx]);
        acc += wx[tx] * s;
    }
    g_rimg[gid] = acc;
}

// ============================================================
// Stage 2: conv1 5x5 stride 2 SAME (pad lo=1, hi=2), 1->32, ReLU
// output layout [b][c][y][x]
// ============================================================
__global__ void conv1_kernel(const float* __restrict__ w1, const float* __restrict__ b1) {
    __shared__ float tile[35 * 35];
    __shared__ float ws[800];
    __shared__ float bs[32];

    int b   = blockIdx.z;
    int py0 = blockIdx.y * 16;
    int px0 = blockIdx.x * 16;
    int tid = threadIdx.x;   // 256

    for (int i = tid; i < 800; i += 256) ws[i] = w1[i];
    if (tid < 32) bs[tid] = b1[tid];
    for (int i = tid; i < 35 * 35; i += 256) {
        int r = i / 35, c = i % 35;
        int gy = 2 * py0 - 1 + r;
        int gx = 2 * px0 - 1 + c;
        float v = 0.0f;
        if (gy >= 0 && gy < HS && gx >= 0 && gx < WS)
            v = g_rimg[(b * HS + gy) * WS + gx];
        tile[i] = v;
    }
    __syncthreads();

    int ty = tid / 16, tx = tid % 16;
    float acc[NCH];
#pragma unroll
    for (int c = 0; c < NCH; c++) acc[c] = 0.0f;

#pragma unroll
    for (int u = 0; u < 5; u++) {
#pragma unroll
        for (int v = 0; v < 5; v++) {
            float s = tile[(2 * ty + u) * 35 + (2 * tx + v)];
            const float* wp = &ws[(u * 5 + v) * NCH];
#pragma unroll
            for (int c = 0; c < NCH; c++) acc[c] += s * wp[c];
        }
    }
    int py = py0 + ty, px = px0 + tx;
#pragma unroll
    for (int c = 0; c < NCH; c++) {
        float hv = acc[c] + bs[c];
        hv = hv > 0.0f ? hv : 0.0f;
        g_h[((b * NCH + c) * HC + py) * WC + px] = hv;
    }
}

// ============================================================
// Stage 3: conv2 5x5 stride 1 SAME (pad 2), 32->1, sigmoid
// EXACT R1 accumulation order (bit-stability of cms is required:
// saturated sigmoid clusters top peaks within ulps, so the top-32
// boundary depends on exact arithmetic order).
// ============================================================
__global__ void conv2_kernel(const float* __restrict__ w2, const float* __restrict__ b2) {
    __shared__ float hs[16 * 400];   // 16 channels x 20x20 tile
    __shared__ float ws[800];

    int b   = blockIdx.z;
    int py0 = blockIdx.y * 16;
    int px0 = blockIdx.x * 16;
    int tid = threadIdx.x;
    int ty = tid / 16, tx = tid % 16;

    for (int i = tid; i < 800; i += 256) ws[i] = w2[i];

    float acc = 0.0f;
    for (int c0 = 0; c0 < NCH; c0 += 16) {
        __syncthreads();
        for (int i = tid; i < 16 * 400; i += 256) {
            int c   = i / 400;
            int r   = (i % 400) / 20;
            int col = i % 20;
            int gy = py0 - 2 + r;
            int gx = px0 - 2 + col;
            float v = 0.0f;
            if (gy >= 0 && gy < HC && gx >= 0 && gx < WC)
                v = g_h[((b * NCH + c0 + c) * HC + gy) * WC + gx];
            hs[i] = v;
        }
        __syncthreads();
        for (int c = 0; c < 16; c++) {
#pragma unroll
            for (int u = 0; u < 5; u++)
#pragma unroll
                for (int v = 0; v < 5; v++)
                    acc += hs[c * 400 + (ty + u) * 20 + (tx + v)] *
                           ws[(u * 5 + v) * NCH + c0 + c];
        }
    }
    float x = acc + b2[0];
    float s = 1.0f / (1.0f + expf(-x));
    g_cms[(b * HC + py0 + ty) * WC + px0 + tx] = s;
}

// ============================================================
// Stage 4: tiled 3x3 NMS + threshold -> packed candidates
// key = (float_bits(val) << 32) | ~idx  (max-key == jax top_k order)
// ============================================================
__global__ void nms_kernel() {
    __shared__ float t[18 * 18];
    __shared__ int cnt_s;
    __shared__ int base_s;

    int b   = blockIdx.z;
    int py0 = blockIdx.y * 16;
    int px0 = blockIdx.x * 16;
    int tid = threadIdx.x;
    int ty  = tid / 16, tx = tid % 16;

    if (tid == 0) cnt_s = 0;
    for (int i = tid; i < 18 * 18; i += 256) {
        int r = i / 18, c = i % 18;
        int gy = py0 - 1 + r;
        int gx = px0 - 1 + c;
        float v = -1.0f;
        if (gy >= 0 && gy < HC && gx >= 0 && gx < WC)
            v = g_cms[(b * HC + gy) * WC + gx];
        t[i] = v;
    }
    __syncthreads();

    float v = t[(ty + 1) * 18 + (tx + 1)];
    bool ok = (v > 0.2f);
    if (ok) {
#pragma unroll
        for (int dy = -1; dy <= 1; dy++)
#pragma unroll
            for (int dx = -1; dx <= 1; dx++) {
                if (dy == 0 && dx == 0) continue;
                if (t[(ty + 1 + dy) * 18 + (tx + 1 + dx)] > v) ok = false;
            }
    }
    int pos = -1;
    if (ok) pos = atomicAdd(&cnt_s, 1);
    __syncthreads();
    if (tid == 0 && cnt_s > 0) base_s = atomicAdd(&g_cnt[b], cnt_s);
    __syncthreads();
    if (ok) {
        unsigned int rem = (unsigned int)((py0 + ty) * WC + (px0 + tx));
        unsigned int fb = __float_as_uint(v);
        unsigned long long key = ((unsigned long long)fb << 32) | (~rem);
        g_cand[b * CANDMAX + base_s + pos] = key;
    }
}

// ============================================================
// Stage 5: top-32 per batch (single-scan local lists + shfl merge)
//          + integral refinement (5x5 patch)
// ============================================================
__global__ void topk_kernel(float* __restrict__ out_offs,
                            float* __restrict__ out_vals,
                            float* __restrict__ out_valid) {
    __shared__ unsigned long long warpmax[8];
    __shared__ unsigned long long winsh;

    int b = blockIdx.x;
    int tid = threadIdx.x;
    int lane = tid & 31, wid = tid >> 5;
    int n = g_cnt[b];
    if (n > CANDMAX) n = CANDMAX;

    // --- single scan: each thread keeps its top-32 sorted descending ---
    unsigned long long loc[KP];
    int cnt = 0;
    for (int i = tid; i < n; i += 256) {
        unsigned long long key = g_cand[b * CANDMAX + i];
        if (cnt < KP) {
            int j = cnt++;
            while (j > 0 && loc[j - 1] < key) { loc[j] = loc[j - 1]; j--; }
            loc[j] = key;
        } else if (key > loc[KP - 1]) {
            int j = KP - 1;
            while (j > 0 && loc[j - 1] < key) { loc[j] = loc[j - 1]; j--; }
            loc[j] = key;
        }
    }

    // --- 32 rounds of block-wide max extraction ---
    int ptr = 0;
    unsigned long long mykey = 0ULL;   // thread k keeps peak k
    for (int k = 0; k < KP; k++) {
        unsigned long long cand = (ptr < cnt) ? loc[ptr] : 0ULL;
        unsigned long long m = cand;
#pragma unroll
        for (int off = 16; off > 0; off >>= 1) {
            unsigned long long o = __shfl_down_sync(0xffffffffu, m, off);
            if (o > m) m = o;
        }
        if (lane == 0) warpmax[wid] = m;
        __syncthreads();
        if (tid == 0) {
            unsigned long long w = warpmax[0];
#pragma unroll
            for (int i = 1; i < 8; i++) if (warpmax[i] > w) w = warpmax[i];
            winsh = w;
        }
        __syncthreads();
        unsigned long long win = winsh;
        if (win != 0ULL && cand == win) ptr++;   // unique keys: exactly one winner
        if (tid == k) mykey = win;
    }
    __syncthreads();

    // --- refinement: thread k processes peak k ---
    if (tid < KP) {
        int k = tid;
        unsigned long long key = mykey;
        float cx = 80.0f, cy = 80.0f, val = 0.0f, vf = 0.0f;
        float offx = 0.0f, offy = 0.0f;
        if (key != 0ULL) {
            vf = 1.0f;
            unsigned int idx = ~(unsigned int)(key & 0xFFFFFFFFULL);
            val = __uint_as_float((unsigned int)(key >> 32));
            int py = idx / WC, px = idx % WC;
            float sum = 0.0f, sx = 0.0f, sy = 0.0f;
            for (int dy = -2; dy <= 2; dy++) {
                for (int dx = -2; dx <= 2; dx++) {
                    int yy = py + dy, xx = px + dx;
                    if (yy >= 0 && yy < HC && xx >= 0 && xx < WC) {
                        float pv = g_cms[(b * HC + yy) * WC + xx];
                        sum += pv;
                        sx += pv * (float)dx;
                        sy += pv * (float)dy;
                    }
                }
            }
            float g = sum + 1e-12f;
            float dxo = sx / g;
            float dyo = sy / g;
            cx = ((float)px + dxo) * 2.0f / 0.5f;
            cy = ((float)py + dyo) * 2.0f / 0.5f;
            offx = cx - 80.0f;
            offy = cy - 80.0f;
        }
        out_vals[b * KP + k] = val;
        out_valid[b * KP + k] = vf;
        out_offs[(b * KP + k) * 2 + 0] = offx;
        out_offs[(b * KP + k) * 2 + 1] = offy;
        g_centers[(b * KP + k) * 3 + 0] = cx;
        g_centers[(b * KP + k) * 3 + 1] = cy;
        g_centers[(b * KP + k) * 3 + 2] = vf;
    }
}

// ============================================================
// Stage 6: bilinear 160x160 crops from full image
// ============================================================
__global__ void crop_kernel(const float* __restrict__ img, float* __restrict__ out) {
    int b = blockIdx.z, k = blockIdx.y, i = blockIdx.x;
    int j = threadIdx.x;

    float cx = g_centers[(b * KP + k) * 3 + 0];
    float cy = g_centers[(b * KP + k) * 3 + 1];
    float vf = g_centers[(b * KP + k) * 3 + 2];

    float sy = (cy - 79.5f) + (float)i;
    float sx = (cx - 79.5f) + (float)j;
    float y0 = floorf(sy), x0 = floorf(sx);
    float wy = sy - y0, wx = sx - x0;
    int y0i = (int)y0, x0i = (int)x0;
    int yi0 = min(max(y0i, 0), H - 1);
    int yi1 = min(max(y0i + 1, 0), H - 1);
    int xi0 = min(max(x0i, 0), W - 1);
    int xi1 = min(max(x0i + 1, 0), W - 1);

    const float* ib = img + (long long)b * H * W;
    float v00 = __ldg(ib + yi0 * W + xi0);
    float v01 = __ldg(ib + yi0 * W + xi1);
    float v10 = __ldg(ib + yi1 * W + xi0);
    float v11 = __ldg(ib + yi1 * W + xi1);

    float top = v00 * (1.0f - wx) + v01 * wx;
    float bot = v10 * (1.0f - wx) + v11 * wx;
    float val = top * (1.0f - wy) + bot * wy;

    float inr = (sy >= 0.0f && sy <= (float)(H - 1) &&
                 sx >= 0.0f && sx <= (float)(W - 1)) ? 1.0f : 0.0f;

    out[(((long long)(b * KP + k)) * CROP + i) * CROP + j] = val * inr * vf;
}

// ============================================================
extern "C" void kernel_launch(void* const* d_in, const int* in_sizes, int n_in,
                              void* d_out, int out_size) {
    const float* img = (const float*)d_in[0];
    const float* w1  = (const float*)d_in[1];
    const float* b1  = (const float*)d_in[2];
    const float* w2  = (const float*)d_in[3];
    const float* b2  = (const float*)d_in[4];

    float* out = (float*)d_out;
    float* out_crops = out;
    float* out_offs  = out + (long long)B * KP * CROP * CROP;
    float* out_vals  = out_offs + B * KP * 2;
    float* out_valid = out_vals + B * KP;

    int n1 = B * HS * WS;
    resize_kernel<<<(n1 + 255) / 256, 256>>>(img);

    dim3 gconv1(WC / 16, HC / 16, B);
    conv1_kernel<<<gconv1, 256>>>(w1, b1);

    dim3 gconv2(WC / 16, HC / 16, B);
    conv2_kernel<<<gconv2, 256>>>(w2, b2);

    dim3 gnms(WC / 16, HC / 16, B);
    nms_kernel<<<gnms, 256>>>();

    topk_kernel<<<B, 256>>>(out_offs, out_vals, out_valid);

    dim3 gcrop(CROP, KP, B);
    crop_kernel<<<gcrop, CROP>>>(img, out_crops);
}

// round 6
// speedup vs baseline: 1.6883x; 1.5258x over previous
#include <cuda_runtime.h>
#include <math.h>

#define B   16
#define H   1024
#define W   1024
#define HS  512
#define WS  512
#define HC  256
#define WC  256
#define KP  32
#define CROP 160
#define NCH 32
#define CANDMAX 65536

// ---- scratch (device globals; no runtime allocation allowed) ----
__device__ float g_rimg[B * HS * WS];            // 16 MB
__device__ float g_h[B * NCH * HC * WC];         // 134 MB, [b][c][y][x]
__device__ float g_cms[B * HC * WC];             // 4 MB
__device__ unsigned long long g_cand[B * CANDMAX];
__device__ int   g_cnt[B];
__device__ float g_centers[B * KP * 3];          // cx, cy, validf

// ============================================================
// Stage 1: antialiased bilinear 2x downsample (jax semantics)
// ============================================================
__device__ __forceinline__ void resize_taps(int o, int n, int* idx, float* w) {
    const float wb = 0.375f / 0.875f;   // edge-renormalized
    const float ws = 0.125f / 0.875f;
    if (o == 0) {
        idx[0] = 0; w[0] = 0.0f;
        idx[1] = 0; w[1] = wb;
        idx[2] = 1; w[2] = wb;
        idx[3] = 2; w[3] = ws;
    } else if (o == n - 1) {
        idx[0] = 2 * o - 1; w[0] = ws;
        idx[1] = 2 * o;     w[1] = wb;
        idx[2] = 2 * o + 1; w[2] = wb;
        idx[3] = 2 * o + 1; w[3] = 0.0f;
    } else {
        idx[0] = 2 * o - 1; w[0] = 0.125f;
        idx[1] = 2 * o;     w[1] = 0.375f;
        idx[2] = 2 * o + 1; w[2] = 0.375f;
        idx[3] = 2 * o + 2; w[3] = 0.125f;
    }
}

__global__ void resize_kernel(const float* __restrict__ img) {
    int gid = blockIdx.x * blockDim.x + threadIdx.x;
    if (gid < B) g_cnt[gid] = 0;     // reset candidate counters each replay
    if (gid >= B * HS * WS) return;
    int b   = gid / (HS * WS);
    int rem = gid % (HS * WS);
    int oy  = rem / WS;
    int ox  = rem % WS;

    int iy[4], ix[4];
    float wy[4], wx[4];
    resize_taps(oy, HS, iy, wy);
    resize_taps(ox, WS, ix, wx);

    const float* ib = img + (long long)b * H * W;
    float acc = 0.0f;
#pragma unroll
    for (int tx = 0; tx < 4; tx++) {
        float s = 0.0f;
#pragma unroll
        for (int ty = 0; ty < 4; ty++)
            s += wy[ty] * __ldg(ib + iy[ty] * W + ix[tx]);
        acc += wx[tx] * s;
    }
    g_rimg[gid] = acc;
}

// ============================================================
// Stage 2: conv1 5x5 stride 2 SAME (pad lo=1, hi=2), 1->32, ReLU
// Per-output-channel FMA chain: (u,v) ascending — EXACT R1 order.
// Weights read as broadcast float4s (LDS.128) to cut LDS count 4x.
// ============================================================
__global__ void conv1_kernel(const float* __restrict__ w1, const float* __restrict__ b1) {
    __shared__ __align__(16) float tile[35 * 35];
    __shared__ __align__(16) float ws[800];
    __shared__ float bs[32];

    int b   = blockIdx.z;
    int py0 = blockIdx.y * 16;
    int px0 = blockIdx.x * 16;
    int tid = threadIdx.x;   // 256

    for (int i = tid; i < 800; i += 256) ws[i] = w1[i];
    if (tid < 32) bs[tid] = b1[tid];
    for (int i = tid; i < 35 * 35; i += 256) {
        int r = i / 35, c = i % 35;
        int gy = 2 * py0 - 1 + r;
        int gx = 2 * px0 - 1 + c;
        float v = 0.0f;
        if (gy >= 0 && gy < HS && gx >= 0 && gx < WS)
            v = g_rimg[(b * HS + gy) * WS + gx];
        tile[i] = v;
    }
    __syncthreads();

    int ty = tid / 16, tx = tid % 16;
    float acc[NCH];
#pragma unroll
    for (int c = 0; c < NCH; c++) acc[c] = 0.0f;

#pragma unroll
    for (int u = 0; u < 5; u++) {
#pragma unroll
        for (int v = 0; v < 5; v++) {
            float s = tile[(2 * ty + u) * 35 + (2 * tx + v)];
            const float4* wp = (const float4*)&ws[(u * 5 + v) * NCH];
#pragma unroll
            for (int c4 = 0; c4 < 8; c4++) {
                float4 q = wp[c4];
                acc[c4 * 4 + 0] = fmaf(s, q.x, acc[c4 * 4 + 0]);
                acc[c4 * 4 + 1] = fmaf(s, q.y, acc[c4 * 4 + 1]);
                acc[c4 * 4 + 2] = fmaf(s, q.z, acc[c4 * 4 + 2]);
                acc[c4 * 4 + 3] = fmaf(s, q.w, acc[c4 * 4 + 3]);
            }
        }
    }
    int py = py0 + ty, px = px0 + tx;
#pragma unroll
    for (int c = 0; c < NCH; c++) {
        float hv = acc[c] + bs[c];
        hv = hv > 0.0f ? hv : 0.0f;
        g_h[((b * NCH + c) * HC + py) * WC + px] = hv;
    }
}

// ============================================================
// Stage 3: conv2 5x5 stride 1 SAME (pad 2), 32->1, sigmoid
// 32x32 tile, 2x2 outputs per thread, 8-ch chunks.
// Each output's accumulation is an explicit fmaf chain in
// (c ascending, u, v) order — BIT-IDENTICAL to the R1 kernel.
// Weights pre-transposed in smem (28-float padded rows) for
// float4 hoists; hs rows read as aligned float2.
// ============================================================
#define C2_CH 8
#define HSTR 38
__global__ void conv2_kernel(const float* __restrict__ w2, const float* __restrict__ b2) {
    __shared__ __align__(16) float hs[C2_CH * 36 * HSTR];   // 43776 B
    __shared__ __align__(16) float wt[32 * 28];             // 3584 B transposed

    int b   = blockIdx.z;
    int py0 = blockIdx.y * 32;
    int px0 = blockIdx.x * 32;
    int tid = threadIdx.x;             // 256
    int ty  = tid / 16, tx = tid % 16;
    int ly  = 2 * ty, lx = 2 * tx;

    // transpose: wt[c*28 + uv] = w2[uv*32 + c]
    for (int i = tid; i < 800; i += 256) {
        int c = i % 32, uv = i / 32;
        wt[c * 28 + uv] = w2[uv * 32 + c];
    }

    float a00 = 0.f, a01 = 0.f, a10 = 0.f, a11 = 0.f;

    for (int c0 = 0; c0 < NCH; c0 += C2_CH) {
        __syncthreads();
        for (int i = tid; i < C2_CH * 36 * 36; i += 256) {
            int c   = i / (36 * 36);
            int rem = i % (36 * 36);
            int r   = rem / 36;
            int col = rem % 36;
            int gy = py0 - 2 + r;
            int gx = px0 - 2 + col;
            float v = 0.0f;
            if (gy >= 0 && gy < HC && gx >= 0 && gx < WC)
                v = g_h[((b * NCH + c0 + c) * HC + gy) * WC + gx];
            hs[(c * 36 + r) * HSTR + col] = v;
        }
        __syncthreads();

#pragma unroll
        for (int cc = 0; cc < C2_CH; cc++) {
            int c = c0 + cc;
            // hoist 25 weights for channel c (6 x LDS.128 + 1 scalar)
            float w[25];
            const float4* wp = (const float4*)&wt[c * 28];
            {
                float4 q0 = wp[0], q1 = wp[1], q2 = wp[2];
                float4 q3 = wp[3], q4 = wp[4], q5 = wp[5];
                w[0]=q0.x; w[1]=q0.y; w[2]=q0.z; w[3]=q0.w;
                w[4]=q1.x; w[5]=q1.y; w[6]=q1.z; w[7]=q1.w;
                w[8]=q2.x; w[9]=q2.y; w[10]=q2.z; w[11]=q2.w;
                w[12]=q3.x; w[13]=q3.y; w[14]=q3.z; w[15]=q3.w;
                w[16]=q4.x; w[17]=q4.y; w[18]=q4.z; w[19]=q4.w;
                w[20]=q5.x; w[21]=q5.y; w[22]=q5.z; w[23]=q5.w;
                w[24] = wt[c * 28 + 24];
            }
#pragma unroll
            for (int u = 0; u < 6; u++) {
                const float* hp = &hs[(cc * 36 + ly + u) * HSTR + lx];
                float2 p0 = *(const float2*)(hp);
                float2 p1 = *(const float2*)(hp + 2);
                float2 p2 = *(const float2*)(hp + 4);
                float v0 = p0.x, v1 = p0.y, v2 = p1.x;
                float v3 = p1.y, v4 = p2.x, v5 = p2.y;
                if (u < 5) {
                    const int o = u * 5;
                    a00 = fmaf(v0, w[o+0], a00); a00 = fmaf(v1, w[o+1], a00);
                    a00 = fmaf(v2, w[o+2], a00); a00 = fmaf(v3, w[o+3], a00);
                    a00 = fmaf(v4, w[o+4], a00);
                    a01 = fmaf(v1, w[o+0], a01); a01 = fmaf(v2, w[o+1], a01);
                    a01 = fmaf(v3, w[o+2], a01); a01 = fmaf(v4, w[o+3], a01);
                    a01 = fmaf(v5, w[o+4], a01);
                }
                if (u > 0) {
                    const int o = (u - 1) * 5;
                    a10 = fmaf(v0, w[o+0], a10); a10 = fmaf(v1, w[o+1], a10);
                    a10 = fmaf(v2, w[o+2], a10); a10 = fmaf(v3, w[o+3], a10);
                    a10 = fmaf(v4, w[o+4], a10);
                    a11 = fmaf(v1, w[o+0], a11); a11 = fmaf(v2, w[o+1], a11);
                    a11 = fmaf(v3, w[o+2], a11); a11 = fmaf(v4, w[o+3], a11);
                    a11 = fmaf(v5, w[o+4], a11);
                }
            }
        }
    }

    float bias = b2[0];
    int oy = py0 + ly, ox = px0 + lx;
    g_cms[(b * HC + oy    ) * WC + ox    ] = 1.0f / (1.0f + expf(-(a00 + bias)));
    g_cms[(b * HC + oy    ) * WC + ox + 1] = 1.0f / (1.0f + expf(-(a01 + bias)));
    g_cms[(b * HC + oy + 1) * WC + ox    ] = 1.0f / (1.0f + expf(-(a10 + bias)));
    g_cms[(b * HC + oy + 1) * WC + ox + 1] = 1.0f / (1.0f + expf(-(a11 + bias)));
}

// ============================================================
// Stage 4: tiled 3x3 NMS + threshold -> packed candidates
// key = (float_bits(val) << 32) | ~idx  (max-key == jax top_k order)
// ============================================================
__global__ void nms_kernel() {
    __shared__ float t[18 * 18];
    __shared__ int cnt_s;
    __shared__ int base_s;

    int b   = blockIdx.z;
    int py0 = blockIdx.y * 16;
    int px0 = blockIdx.x * 16;
    int tid = threadIdx.x;
    int ty  = tid / 16, tx = tid % 16;

    if (tid == 0) cnt_s = 0;
    for (int i = tid; i < 18 * 18; i += 256) {
        int r = i / 18, c = i % 18;
        int gy = py0 - 1 + r;
        int gx = px0 - 1 + c;
        float v = -1.0f;
        if (gy >= 0 && gy < HC && gx >= 0 && gx < WC)
            v = g_cms[(b * HC + gy) * WC + gx];
        t[i] = v;
    }
    __syncthreads();

    float v = t[(ty + 1) * 18 + (tx + 1)];
    bool ok = (v > 0.2f);
    if (ok) {
#pragma unroll
        for (int dy = -1; dy <= 1; dy++)
#pragma unroll
            for (int dx = -1; dx <= 1; dx++) {
                if (dy == 0 && dx == 0) continue;
                if (t[(ty + 1 + dy) * 18 + (tx + 1 + dx)] > v) ok = false;
            }
    }
    int pos = -1;
    if (ok) pos = atomicAdd(&cnt_s, 1);
    __syncthreads();
    if (tid == 0 && cnt_s > 0) base_s = atomicAdd(&g_cnt[b], cnt_s);
    __syncthreads();
    if (ok) {
        unsigned int rem = (unsigned int)((py0 + ty) * WC + (px0 + tx));
        unsigned int fb = __float_as_uint(v);
        unsigned long long key = ((unsigned long long)fb << 32) | (~rem);
        g_cand[b * CANDMAX + base_s + pos] = key;
    }
}

// ============================================================
// Stage 5: top-32 per batch (single-scan local lists + shfl merge)
//          + integral refinement (5x5 patch)
// ============================================================
__global__ void topk_kernel(float* __restrict__ out_offs,
                            float* __restrict__ out_vals,
                            float* __restrict__ out_valid) {
    __shared__ unsigned long long warpmax[8];
    __shared__ unsigned long long winsh;

    int b = blockIdx.x;
    int tid = threadIdx.x;
    int lane = tid & 31, wid = tid >> 5;
    int n = g_cnt[b];
    if (n > CANDMAX) n = CANDMAX;

    // --- single scan: each thread keeps its top-32 sorted descending ---
    unsigned long long loc[KP];
    int cnt = 0;
    for (int i = tid; i < n; i += 256) {
        unsigned long long key = g_cand[b * CANDMAX + i];
        if (cnt < KP) {
            int j = cnt++;
            while (j > 0 && loc[j - 1] < key) { loc[j] = loc[j - 1]; j--; }
            loc[j] = key;
        } else if (key > loc[KP - 1]) {
            int j = KP - 1;
            while (j > 0 && loc[j - 1] < key) { loc[j] = loc[j - 1]; j--; }
            loc[j] = key;
        }
    }

    // --- 32 rounds of block-wide max extraction ---
    int ptr = 0;
    unsigned long long mykey = 0ULL;   // thread k keeps peak k
    for (int k = 0; k < KP; k++) {
        unsigned long long cand = (ptr < cnt) ? loc[ptr] : 0ULL;
        unsigned long long m = cand;
#pragma unroll
        for (int off = 16; off > 0; off >>= 1) {
            unsigned long long o = __shfl_down_sync(0xffffffffu, m, off);
            if (o > m) m = o;
        }
        if (lane == 0) warpmax[wid] = m;
        __syncthreads();
        if (tid == 0) {
            unsigned long long w = warpmax[0];
#pragma unroll
            for (int i = 1; i < 8; i++) if (warpmax[i] > w) w = warpmax[i];
            winsh = w;
        }
        __syncthreads();
        unsigned long long win = winsh;
        if (win != 0ULL && cand == win) ptr++;   // unique keys: exactly one winner
        if (tid == k) mykey = win;
    }
    __syncthreads();

    // --- refinement: thread k processes peak k ---
    if (tid < KP) {
        int k = tid;
        unsigned long long key = mykey;
        float cx = 80.0f, cy = 80.0f, val = 0.0f, vf = 0.0f;
        float offx = 0.0f, offy = 0.0f;
        if (key != 0ULL) {
            vf = 1.0f;
            unsigned int idx = ~(unsigned int)(key & 0xFFFFFFFFULL);
            val = __uint_as_float((unsigned int)(key >> 32));
            int py = idx / WC, px = idx % WC;
            float sum = 0.0f, sx = 0.0f, sy = 0.0f;
            for (int dy = -2; dy <= 2; dy++) {
                for (int dx = -2; dx <= 2; dx++) {
                    int yy = py + dy, xx = px + dx;
                    if (yy >= 0 && yy < HC && xx >= 0 && xx < WC) {
                        float pv = g_cms[(b * HC + yy) * WC + xx];
                        sum += pv;
                        sx += pv * (float)dx;
                        sy += pv * (float)dy;
                    }
                }
            }
            float g = sum + 1e-12f;
            float dxo = sx / g;
            float dyo = sy / g;
            cx = ((float)px + dxo) * 2.0f / 0.5f;
            cy = ((float)py + dyo) * 2.0f / 0.5f;
            offx = cx - 80.0f;
            offy = cy - 80.0f;
        }
        out_vals[b * KP + k] = val;
        out_valid[b * KP + k] = vf;
        out_offs[(b * KP + k) * 2 + 0] = offx;
        out_offs[(b * KP + k) * 2 + 1] = offy;
        g_centers[(b * KP + k) * 3 + 0] = cx;
        g_centers[(b * KP + k) * 3 + 1] = cy;
        g_centers[(b * KP + k) * 3 + 2] = vf;
    }
}

// ============================================================
// Stage 6: bilinear 160x160 crops from full image
// ============================================================
__global__ void crop_kernel(const float* __restrict__ img, float* __restrict__ out) {
    int b = blockIdx.z, k = blockIdx.y, i = blockIdx.x;
    int j = threadIdx.x;

    float cx = g_centers[(b * KP + k) * 3 + 0];
    float cy = g_centers[(b * KP + k) * 3 + 1];
    float vf = g_centers[(b * KP + k) * 3 + 2];

    float sy = (cy - 79.5f) + (float)i;
    float sx = (cx - 79.5f) + (float)j;
    float y0 = floorf(sy), x0 = floorf(sx);
    float wy = sy - y0, wx = sx - x0;
    int y0i = (int)y0, x0i = (int)x0;
    int yi0 = min(max(y0i, 0), H - 1);
    int yi1 = min(max(y0i + 1, 0), H - 1);
    int xi0 = min(max(x0i, 0), W - 1);
    int xi1 = min(max(x0i + 1, 0), W - 1);

    const float* ib = img + (long long)b * H * W;
    float v00 = __ldg(ib + yi0 * W + xi0);
    float v01 = __ldg(ib + yi0 * W + xi1);
    float v10 = __ldg(ib + yi1 * W + xi0);
    float v11 = __ldg(ib + yi1 * W + xi1);

    float top = v00 * (1.0f - wx) + v01 * wx;
    float bot = v10 * (1.0f - wx) + v11 * wx;
    float val = top * (1.0f - wy) + bot * wy;

    float inr = (sy >= 0.0f && sy <= (float)(H - 1) &&
                 sx >= 0.0f && sx <= (float)(W - 1)) ? 1.0f : 0.0f;

    out[(((long long)(b * KP + k)) * CROP + i) * CROP + j] = val * inr * vf;
}

// ============================================================
extern "C" void kernel_launch(void* const* d_in, const int* in_sizes, int n_in,
                              void* d_out, int out_size) {
    const float* img = (const float*)d_in[0];
    const float* w1  = (const float*)d_in[1];
    const float* b1  = (const float*)d_in[2];
    const float* w2  = (const float*)d_in[3];
    const float* b2  = (const float*)d_in[4];

    float* out = (float*)d_out;
    float* out_crops = out;
    float* out_offs  = out + (long long)B * KP * CROP * CROP;
    float* out_vals  = out_offs + B * KP * 2;
    float* out_valid = out_vals + B * KP;

    int n1 = B * HS * WS;
    resize_kernel<<<(n1 + 255) / 256, 256>>>(img);

    dim3 gconv1(WC / 16, HC / 16, B);
    conv1_kernel<<<gconv1, 256>>>(w1, b1);

    dim3 gconv2(WC / 32, HC / 32, B);
    conv2_kernel<<<gconv2, 256>>>(w2, b2);

    dim3 gnms(WC / 16, HC / 16, B);
    nms_kernel<<<gnms, 256>>>();

    topk_kernel<<<B, 256>>>(out_offs, out_vals, out_valid);

    dim3 gcrop(CROP, KP, B);
    crop_kernel<<<gcrop, CROP>>>(img, out_crops);
}

// round 7
// speedup vs baseline: 2.1658x; 1.2828x over previous
#include <cuda_runtime.h>
#include <math.h>

#define B   16
#define H   1024
#define W   1024
#define HS  512
#define WS  512
#define HC  256
#define WC  256
#define KP  32
#define CROP 160
#define NCH 32
#define CANDMAX 65536

// ---- scratch (device globals; no runtime allocation allowed) ----
__device__ float g_rimg[B * HS * WS];            // 16 MB
__device__ float g_cms[B * HC * WC];             // 4 MB
__device__ unsigned long long g_cand[B * CANDMAX];
__device__ int   g_cnt[B];
__device__ float g_centers[B * KP * 3];          // cx, cy, validf

// ============================================================
// Stage 1: antialiased bilinear 2x downsample (jax semantics)
// ============================================================
__device__ __forceinline__ void resize_taps(int o, int n, int* idx, float* w) {
    const float wb = 0.375f / 0.875f;   // edge-renormalized
    const float ws = 0.125f / 0.875f;
    if (o == 0) {
        idx[0] = 0; w[0] = 0.0f;
        idx[1] = 0; w[1] = wb;
        idx[2] = 1; w[2] = wb;
        idx[3] = 2; w[3] = ws;
    } else if (o == n - 1) {
        idx[0] = 2 * o - 1; w[0] = ws;
        idx[1] = 2 * o;     w[1] = wb;
        idx[2] = 2 * o + 1; w[2] = wb;
        idx[3] = 2 * o + 1; w[3] = 0.0f;
    } else {
        idx[0] = 2 * o - 1; w[0] = 0.125f;
        idx[1] = 2 * o;     w[1] = 0.375f;
        idx[2] = 2 * o + 1; w[2] = 0.375f;
        idx[3] = 2 * o + 2; w[3] = 0.125f;
    }
}

__global__ void resize_kernel(const float* __restrict__ img) {
    int gid = blockIdx.x * blockDim.x + threadIdx.x;
    if (gid < B) g_cnt[gid] = 0;     // reset candidate counters each replay
    if (gid >= B * HS * WS) return;
    int b   = gid / (HS * WS);
    int rem = gid % (HS * WS);
    int oy  = rem / WS;
    int ox  = rem % WS;

    int iy[4], ix[4];
    float wy[4], wx[4];
    resize_taps(oy, HS, iy, wy);
    resize_taps(ox, WS, ix, wx);

    const float* ib = img + (long long)b * H * W;
    float acc = 0.0f;
#pragma unroll
    for (int tx = 0; tx < 4; tx++) {
        float s = 0.0f;
#pragma unroll
        for (int ty = 0; ty < 4; ty++)
            s += wy[ty] * __ldg(ib + iy[ty] * W + ix[tx]);
        acc += wx[tx] * s;
    }
    g_rimg[gid] = acc;
}

// ============================================================
// Stage 2+3 FUSED: conv1 (5x5 s2, 1->32, ReLU) + conv2 (5x5 s1,
// 32->1, sigmoid), no global h round-trip.
// Per 32x32 output tile: 75x75 rimg halo in smem; per 8-channel
// chunk, recompute the 36x36 h halo into smem, then run the
// R4-validated conv2 chunk accumulation against it.
// BIT-EXACT chains: conv1 per (pos,channel) fmaf over (u,v)
// ascending; conv2 per output fmaf over (c asc, u, v). h outside
// [0,256)^2 forced to 0 (SAME zero padding).
// ============================================================
#define RTS   76        // rimg tile row stride (75 cols + pad)
#define H2S   38        // h tile row stride (36 cols + pad)
#define OFF_RT  0                      // 75*76  = 5700 floats
#define OFF_H   5700                   // 8*36*38 = 10944 floats
#define OFF_W1  16644                  // 800 floats
#define OFF_WT2 17444                  // 32*28 = 896 floats
#define OFF_BS  18340                  // 32 floats
#define FUSED_SMEM_FLOATS 18372
#define FUSED_SMEM_BYTES  (FUSED_SMEM_FLOATS * 4)

__global__ void fused_conv_kernel(const float* __restrict__ w1,
                                  const float* __restrict__ b1,
                                  const float* __restrict__ w2,
                                  const float* __restrict__ b2) {
    extern __shared__ __align__(16) float sm[];
    float* rt  = sm + OFF_RT;    // [75][76]
    float* hsm = sm + OFF_H;     // [8][36][38]
    float* w1s = sm + OFF_W1;    // [25][32]
    float* wt2 = sm + OFF_WT2;   // [32][28] transposed conv2 weights
    float* bs1 = sm + OFF_BS;    // [32]

    int b   = blockIdx.z;
    int py0 = blockIdx.y * 32;
    int px0 = blockIdx.x * 32;
    int tid = threadIdx.x;             // 256
    int ty  = tid / 16, tx = tid % 16;
    int ly  = 2 * ty, lx = 2 * tx;

    for (int i = tid; i < 800; i += 256) w1s[i] = w1[i];
    for (int i = tid; i < 800; i += 256) {
        int c = i % 32, uv = i / 32;
        wt2[c * 28 + uv] = w2[i];      // w2[uv*32+c]
    }
    if (tid < 32) bs1[tid] = b1[tid];

    // rimg halo: rows 2*py0-5 .. 2*py0+69, cols likewise (75x75)
    for (int i = tid; i < 75 * 75; i += 256) {
        int r = i / 75, c = i % 75;
        int gy = 2 * py0 - 5 + r;
        int gx = 2 * px0 - 5 + c;
        float v = 0.0f;
        if (gy >= 0 && gy < HS && gx >= 0 && gx < WS)
            v = g_rimg[(b * HS + gy) * WS + gx];
        rt[r * RTS + c] = v;
    }

    // h positions handled by this thread (up to 6 of 1296)
    int off[6];        // rimg window start offset (2r*RTS + 2cl)
    int sidx[6];       // hsm store index (r*H2S + cl), channel added later
    int val[6];        // 1 if h position is inside [0,256)^2
#pragma unroll
    for (int p = 0; p < 6; p++) {
        int i = tid + p * 256;
        if (i < 1296) {
            int r = i / 36, cl = i % 36;
            off[p]  = 2 * r * RTS + 2 * cl;
            sidx[p] = r * H2S + cl;
            int hy = py0 - 2 + r, hx = px0 - 2 + cl;
            val[p] = (hy >= 0 && hy < HC && hx >= 0 && hx < WC) ? 1 : 0;
        } else {
            off[p] = 0; sidx[p] = 0; val[p] = -1;   // -1 => no store
        }
    }

    float a00 = 0.f, a01 = 0.f, a10 = 0.f, a11 = 0.f;

    for (int c0 = 0; c0 < NCH; c0 += 8) {
        __syncthreads();   // hsm reuse + (first iter) initial loads

        // ---- conv1 chunk: 8 channels, taps outer, positions inner ----
        float acc[6][8];
#pragma unroll
        for (int p = 0; p < 6; p++)
#pragma unroll
            for (int k = 0; k < 8; k++) acc[p][k] = 0.0f;

#pragma unroll
        for (int u = 0; u < 5; u++) {
#pragma unroll
            for (int v = 0; v < 5; v++) {
                const float4* wp = (const float4*)&w1s[(u * 5 + v) * NCH + c0];
                float4 qa = wp[0], qb = wp[1];
#pragma unroll
                for (int p = 0; p < 6; p++) {
                    if (p == 5 && val[5] < 0) continue;
                    float s = rt[off[p] + u * RTS + v];
                    acc[p][0] = fmaf(s, qa.x, acc[p][0]);
                    acc[p][1] = fmaf(s, qa.y, acc[p][1]);
                    acc[p][2] = fmaf(s, qa.z, acc[p][2]);
                    acc[p][3] = fmaf(s, qa.w, acc[p][3]);
                    acc[p][4] = fmaf(s, qb.x, acc[p][4]);
                    acc[p][5] = fmaf(s, qb.y, acc[p][5]);
                    acc[p][6] = fmaf(s, qb.z, acc[p][6]);
                    acc[p][7] = fmaf(s, qb.w, acc[p][7]);
                }
            }
        }
#pragma unroll
        for (int p = 0; p < 6; p++) {
            if (val[p] < 0) continue;
#pragma unroll
            for (int k = 0; k < 8; k++) {
                float hv = 0.0f;
                if (val[p]) {
                    hv = acc[p][k] + bs1[c0 + k];
                    hv = hv > 0.0f ? hv : 0.0f;
                }
                hsm[k * (36 * H2S) + sidx[p]] = hv;
            }
        }
        __syncthreads();

        // ---- conv2 chunk: EXACT R4-validated accumulation ----
#pragma unroll
        for (int cc = 0; cc < 8; cc++) {
            int c = c0 + cc;
            float w[25];
            const float4* wp = (const float4*)&wt2[c * 28];
            {
                float4 q0 = wp[0], q1 = wp[1], q2 = wp[2];
                float4 q3 = wp[3], q4 = wp[4], q5 = wp[5];
                w[0]=q0.x; w[1]=q0.y; w[2]=q0.z; w[3]=q0.w;
                w[4]=q1.x; w[5]=q1.y; w[6]=q1.z; w[7]=q1.w;
                w[8]=q2.x; w[9]=q2.y; w[10]=q2.z; w[11]=q2.w;
                w[12]=q3.x; w[13]=q3.y; w[14]=q3.z; w[15]=q3.w;
                w[16]=q4.x; w[17]=q4.y; w[18]=q4.z; w[19]=q4.w;
                w[20]=q5.x; w[21]=q5.y; w[22]=q5.z; w[23]=q5.w;
                w[24] = wt2[c * 28 + 24];
            }
#pragma unroll
            for (int u = 0; u < 6; u++) {
                const float* hp = &hsm[(cc * 36 + ly + u) * H2S + lx];
                float2 p0 = *(const float2*)(hp);
                float2 p1 = *(const float2*)(hp + 2);
                float2 p2 = *(const float2*)(hp + 4);
                float v0 = p0.x, v1 = p0.y, v2 = p1.x;
                float v3 = p1.y, v4 = p2.x, v5 = p2.y;
                if (u < 5) {
                    const int o = u * 5;
                    a00 = fmaf(v0, w[o+0], a00); a00 = fmaf(v1, w[o+1], a00);
                    a00 = fmaf(v2, w[o+2], a00); a00 = fmaf(v3, w[o+3], a00);
                    a00 = fmaf(v4, w[o+4], a00);
                    a01 = fmaf(v1, w[o+0], a01); a01 = fmaf(v2, w[o+1], a01);
                    a01 = fmaf(v3, w[o+2], a01); a01 = fmaf(v4, w[o+3], a01);
                    a01 = fmaf(v5, w[o+4], a01);
                }
                if (u > 0) {
                    const int o = (u - 1) * 5;
                    a10 = fmaf(v0, w[o+0], a10); a10 = fmaf(v1, w[o+1], a10);
                    a10 = fmaf(v2, w[o+2], a10); a10 = fmaf(v3, w[o+3], a10);
                    a10 = fmaf(v4, w[o+4], a10);
                    a11 = fmaf(v1, w[o+0], a11); a11 = fmaf(v2, w[o+1], a11);
                    a11 = fmaf(v3, w[o+2], a11); a11 = fmaf(v4, w[o+3], a11);
                    a11 = fmaf(v5, w[o+4], a11);
                }
            }
        }
    }

    float bias = __ldg(b2);
    int oy = py0 + ly, ox = px0 + lx;
    g_cms[(b * HC + oy    ) * WC + ox    ] = 1.0f / (1.0f + expf(-(a00 + bias)));
    g_cms[(b * HC + oy    ) * WC + ox + 1] = 1.0f / (1.0f + expf(-(a01 + bias)));
    g_cms[(b * HC + oy + 1) * WC + ox    ] = 1.0f / (1.0f + expf(-(a10 + bias)));
    g_cms[(b * HC + oy + 1) * WC + ox + 1] = 1.0f / (1.0f + expf(-(a11 + bias)));
}

// ============================================================
// Stage 4: tiled 3x3 NMS + threshold -> packed candidates
// key = (float_bits(val) << 32) | ~idx  (max-key == jax top_k order)
// ============================================================
__global__ void nms_kernel() {
    __shared__ float t[18 * 18];
    __shared__ int cnt_s;
    __shared__ int base_s;

    int b   = blockIdx.z;
    int py0 = blockIdx.y * 16;
    int px0 = blockIdx.x * 16;
    int tid = threadIdx.x;
    int ty  = tid / 16, tx = tid % 16;

    if (tid == 0) cnt_s = 0;
    for (int i = tid; i < 18 * 18; i += 256) {
        int r = i / 18, c = i % 18;
        int gy = py0 - 1 + r;
        int gx = px0 - 1 + c;
        float v = -1.0f;
        if (gy >= 0 && gy < HC && gx >= 0 && gx < WC)
            v = g_cms[(b * HC + gy) * WC + gx];
        t[i] = v;
    }
    __syncthreads();

    float v = t[(ty + 1) * 18 + (tx + 1)];
    bool ok = (v > 0.2f);
    if (ok) {
#pragma unroll
        for (int dy = -1; dy <= 1; dy++)
#pragma unroll
            for (int dx = -1; dx <= 1; dx++) {
                if (dy == 0 && dx == 0) continue;
                if (t[(ty + 1 + dy) * 18 + (tx + 1 + dx)] > v) ok = false;
            }
    }
    int pos = -1;
    if (ok) pos = atomicAdd(&cnt_s, 1);
    __syncthreads();
    if (tid == 0 && cnt_s > 0) base_s = atomicAdd(&g_cnt[b], cnt_s);
    __syncthreads();
    if (ok) {
        unsigned int rem = (unsigned int)((py0 + ty) * WC + (px0 + tx));
        unsigned int fb = __float_as_uint(v);
        unsigned long long key = ((unsigned long long)fb << 32) | (~rem);
        g_cand[b * CANDMAX + base_s + pos] = key;
    }
}

// ============================================================
// Stage 5: top-32 per batch (single-scan local lists + shfl merge)
//          + integral refinement (5x5 patch)
// ============================================================
__global__ void topk_kernel(float* __restrict__ out_offs,
                            float* __restrict__ out_vals,
                            float* __restrict__ out_valid) {
    __shared__ unsigned long long warpmax[8];
    __shared__ unsigned long long winsh;

    int b = blockIdx.x;
    int tid = threadIdx.x;
    int lane = tid & 31, wid = tid >> 5;
    int n = g_cnt[b];
    if (n > CANDMAX) n = CANDMAX;

    // --- single scan: each thread keeps its top-32 sorted descending ---
    unsigned long long loc[KP];
    int cnt = 0;
    for (int i = tid; i < n; i += 256) {
        unsigned long long key = g_cand[b * CANDMAX + i];
        if (cnt < KP) {
            int j = cnt++;
            while (j > 0 && loc[j - 1] < key) { loc[j] = loc[j - 1]; j--; }
            loc[j] = key;
        } else if (key > loc[KP - 1]) {
            int j = KP - 1;
            while (j > 0 && loc[j - 1] < key) { loc[j] = loc[j - 1]; j--; }
            loc[j] = key;
        }
    }

    // --- 32 rounds of block-wide max extraction ---
    int ptr = 0;
    unsigned long long mykey = 0ULL;   // thread k keeps peak k
    for (int k = 0; k < KP; k++) {
        unsigned long long cand = (ptr < cnt) ? loc[ptr] : 0ULL;
        unsigned long long m = cand;
#pragma unroll
        for (int off = 16; off > 0; off >>= 1) {
            unsigned long long o = __shfl_down_sync(0xffffffffu, m, off);
            if (o > m) m = o;
        }
        if (lane == 0) warpmax[wid] = m;
        __syncthreads();
        if (tid == 0) {
            unsigned long long w = warpmax[0];
#pragma unroll
            for (int i = 1; i < 8; i++) if (warpmax[i] > w) w = warpmax[i];
            winsh = w;
        }
        __syncthreads();
        unsigned long long win = winsh;
        if (win != 0ULL && cand == win) ptr++;   // unique keys: exactly one winner
        if (tid == k) mykey = win;
    }
    __syncthreads();

    // --- refinement: thread k processes peak k ---
    if (tid < KP) {
        int k = tid;
        unsigned long long key = mykey;
        float cx = 80.0f, cy = 80.0f, val = 0.0f, vf = 0.0f;
        float offx = 0.0f, offy = 0.0f;
        if (key != 0ULL) {
            vf = 1.0f;
            unsigned int idx = ~(unsigned int)(key & 0xFFFFFFFFULL);
            val = __uint_as_float((unsigned int)(key >> 32));
            int py = idx / WC, px = idx % WC;
            float sum = 0.0f, sx = 0.0f, sy = 0.0f;
            for (int dy = -2; dy <= 2; dy++) {
                for (int dx = -2; dx <= 2; dx++) {
                    int yy = py + dy, xx = px + dx;
                    if (yy >= 0 && yy < HC && xx >= 0 && xx < WC) {
                        float pv = g_cms[(b * HC + yy) * WC + xx];
                        sum += pv;
                        sx += pv * (float)dx;
                        sy += pv * (float)dy;
                    }
                }
            }
            float g = sum + 1e-12f;
            float dxo = sx / g;
            float dyo = sy / g;
            cx = ((float)px + dxo) * 2.0f / 0.5f;
            cy = ((float)py + dyo) * 2.0f / 0.5f;
            offx = cx - 80.0f;
            offy = cy - 80.0f;
        }
        out_vals[b * KP + k] = val;
        out_valid[b * KP + k] = vf;
        out_offs[(b * KP + k) * 2 + 0] = offx;
        out_offs[(b * KP + k) * 2 + 1] = offy;
        g_centers[(b * KP + k) * 3 + 0] = cx;
        g_centers[(b * KP + k) * 3 + 1] = cy;
        g_centers[(b * KP + k) * 3 + 2] = vf;
    }
}

// ============================================================
// Stage 6: bilinear 160x160 crops from full image
// ============================================================
__global__ void crop_kernel(const float* __restrict__ img, float* __restrict__ out) {
    int b = blockIdx.z, k = blockIdx.y, i = blockIdx.x;
    int j = threadIdx.x;

    float cx = g_centers[(b * KP + k) * 3 + 0];
    float cy = g_centers[(b * KP + k) * 3 + 1];
    float vf = g_centers[(b * KP + k) * 3 + 2];

    float sy = (cy - 79.5f) + (float)i;
    float sx = (cx - 79.5f) + (float)j;
    float y0 = floorf(sy), x0 = floorf(sx);
    float wy = sy - y0, wx = sx - x0;
    int y0i = (int)y0, x0i = (int)x0;
    int yi0 = min(max(y0i, 0), H - 1);
    int yi1 = min(max(y0i + 1, 0), H - 1);
    int xi0 = min(max(x0i, 0), W - 1);
    int xi1 = min(max(x0i + 1, 0), W - 1);

    const float* ib = img + (long long)b * H * W;
    float v00 = __ldg(ib + yi0 * W + xi0);
    float v01 = __ldg(ib + yi0 * W + xi1);
    float v10 = __ldg(ib + yi1 * W + xi0);
    float v11 = __ldg(ib + yi1 * W + xi1);

    float top = v00 * (1.0f - wx) + v01 * wx;
    float bot = v10 * (1.0f - wx) + v11 * wx;
    float val = top * (1.0f - wy) + bot * wy;

    float inr = (sy >= 0.0f && sy <= (float)(H - 1) &&
                 sx >= 0.0f && sx <= (float)(W - 1)) ? 1.0f : 0.0f;

    out[(((long long)(b * KP + k)) * CROP + i) * CROP + j] = val * inr * vf;
}

// ============================================================
extern "C" void kernel_launch(void* const* d_in, const int* in_sizes, int n_in,
                              void* d_out, int out_size) {
    const float* img = (const float*)d_in[0];
    const float* w1  = (const float*)d_in[1];
    const float* b1  = (const float*)d_in[2];
    const float* w2  = (const float*)d_in[3];
    const float* b2  = (const float*)d_in[4];

    float* out = (float*)d_out;
    float* out_crops = out;
    float* out_offs  = out + (long long)B * KP * CROP * CROP;
    float* out_vals  = out_offs + B * KP * 2;
    float* out_valid = out_vals + B * KP;

    cudaFuncSetAttribute(fused_conv_kernel,
                         cudaFuncAttributeMaxDynamicSharedMemorySize,
                         FUSED_SMEM_BYTES);

    int n1 = B * HS * WS;
    resize_kernel<<<(n1 + 255) / 256, 256>>>(img);

    dim3 gconv(WC / 32, HC / 32, B);
    fused_conv_kernel<<<gconv, 256, FUSED_SMEM_BYTES>>>(w1, b1, w2, b2);

    dim3 gnms(WC / 16, HC / 16, B);
    nms_kernel<<<gnms, 256>>>();

    topk_kernel<<<B, 256>>>(out_offs, out_vals, out_valid);

    dim3 gcrop(CROP, KP, B);
    crop_kernel<<<gcrop, CROP>>>(img, out_crops);
}